// round 1
// baseline (speedup 1.0000x reference)
#include <cuda_runtime.h>
#include <cuda_bf16.h>

// Problem constants
#define BB   2048
#define CC   6
#define HH   128
#define WW   96
#define OH   32
#define OW   24

// Antialiased triangle filter, scale=0.25 (both dims):
// output o samples at s = 4o + 1.5; taps j = 4o-2 .. 4o+5 with raw weights
// 1 - |s-j|/4 = {1,3,5,7,7,5,3,1}/8; normalized by the sum of in-range taps
// (4.0 interior, 3.5 at the first/last output).

__global__ __launch_bounds__(256)
void resize_aa_kernel(const float* __restrict__ x, float* __restrict__ out) {
    extern __shared__ float smem[];
    float* img = smem;              // HH*WW   = 12288 floats (48 KB)
    float* tmp = smem + HH * WW;    // HH*OW   =  3072 floats (12 KB)

    const int img_id = blockIdx.x;                 // 0 .. B*C-1
    const int tid = threadIdx.x;
    const float* __restrict__ src = x + (size_t)img_id * (HH * WW);

    // ---- Stage full 128x96 image into SMEM (coalesced float4) ----
    {
        const float4* __restrict__ src4 = (const float4*)src;
        float4* img4 = (float4*)img;
        #pragma unroll
        for (int i = tid; i < (HH * WW) / 4; i += 256)
            img4[i] = src4[i];
    }
    __syncthreads();

    const float wt[8] = {0.125f, 0.375f, 0.625f, 0.875f,
                         0.875f, 0.625f, 0.375f, 0.125f};

    // ---- Horizontal pass: tmp[r][oc], r in [0,128), oc in [0,24) ----
    for (int i = tid; i < HH * OW; i += 256) {
        int r  = i / OW;
        int oc = i - r * OW;
        int j0 = 4 * oc - 2;
        float acc = 0.f, s = 0.f;
        const float* row = img + r * WW;
        #pragma unroll
        for (int k = 0; k < 8; k++) {
            int j = j0 + k;
            if (j >= 0 && j < WW) {
                acc += wt[k] * row[j];
                s   += wt[k];
            }
        }
        tmp[i] = acc / s;
    }
    __syncthreads();

    // ---- Vertical pass: out[oh][ow] ----
    float* __restrict__ dst = out + (size_t)img_id * (OH * OW);
    for (int i = tid; i < OH * OW; i += 256) {
        int oh = i / OW;
        int ow = i - oh * OW;
        int j0 = 4 * oh - 2;
        float acc = 0.f, s = 0.f;
        #pragma unroll
        for (int k = 0; k < 8; k++) {
            int j = j0 + k;
            if (j >= 0 && j < HH) {
                acc += wt[k] * tmp[j * OW + ow];
                s   += wt[k];
            }
        }
        dst[i] = acc / s;
    }
}

extern "C" void kernel_launch(void* const* d_in, const int* in_sizes, int n_in,
                              void* d_out, int out_size) {
    const float* x = (const float*)d_in[0];   // (2048, 6, 128, 96) float32
    // d_in[1] = y (int32) is unused by the forward pass.
    float* out = (float*)d_out;               // (2048, 6, 768) float32

    const int smem_bytes = (HH * WW + HH * OW) * (int)sizeof(float); // 61440
    cudaFuncSetAttribute(resize_aa_kernel,
                         cudaFuncAttributeMaxDynamicSharedMemorySize, smem_bytes);

    resize_aa_kernel<<<BB * CC, 256, smem_bytes>>>(x, out);
}

// round 2
// speedup vs baseline: 2.0698x; 2.0698x over previous
#include <cuda_runtime.h>
#include <cuda_bf16.h>

// Problem: batched antialiased bilinear resize (128,96) -> (32,24), scale 1/4.
// Separable triangle filter, support 4: output o samples s=4o+1.5, taps
// j=4o-2..4o+5, raw weights {1,3,5,7,7,5,3,1}/8, normalized by in-range tap
// sum (4.0 interior, 3.5 at first/last output).
//
// Horizontal pass is done in registers via warp shuffles (no SMEM image
// staging): lane oc loads float4 row[4oc..4oc+3]; taps 4oc-2..4oc+5 come from
// (lane-1).zw, own xyzw, (lane+1).xy. Only the 128x24 intermediate touches SMEM.

#define BB   2048
#define CC   6
#define HH   128
#define WW   96
#define OH   32
#define OW   24

__global__ __launch_bounds__(256)
void resize_aa_kernel(const float* __restrict__ x, float* __restrict__ out) {
    __shared__ float tmp[HH * OW];   // 12 KB horizontal intermediate

    const int img_id = blockIdx.x;   // 0 .. B*C-1
    const int tid  = threadIdx.x;
    const int wid  = tid >> 5;
    const int lane = tid & 31;
    const float* __restrict__ src = x + (size_t)img_id * (HH * WW);

    // ---- per-lane horizontal weights (norm folded in) ----
    const int oc = (lane < OW) ? lane : (OW - 1);   // lanes 24..31 shadow lane 23
    float w0 = 0.125f, w1 = 0.375f, w2 = 0.625f, w3 = 0.875f,
          w4 = 0.875f, w5 = 0.625f, w6 = 0.375f, w7 = 0.125f;
    float norm = 0.25f;
    if (oc == 0)      { w0 = 0.f; w1 = 0.f; norm = 1.f / 3.5f; }
    if (oc == OW - 1) { w6 = 0.f; w7 = 0.f; norm = 1.f / 3.5f; }
    w0 *= norm; w1 *= norm; w2 *= norm; w3 *= norm;
    w4 *= norm; w5 *= norm; w6 *= norm; w7 *= norm;

    // ---- horizontal pass: one warp per row, 16 rows per warp ----
    #pragma unroll
    for (int i = 0; i < HH / 8; i++) {
        const int r = wid + 8 * i;
        // coalesced 128-bit load; lanes >=24 duplicate lane 23's data (harmless)
        float4 v = *(const float4*)(src + r * WW + 4 * oc);
        float lz = __shfl_up_sync  (0xFFFFFFFFu, v.z, 1);
        float lw = __shfl_up_sync  (0xFFFFFFFFu, v.w, 1);
        float rx = __shfl_down_sync(0xFFFFFFFFu, v.x, 1);
        float ry = __shfl_down_sync(0xFFFFFFFFu, v.y, 1);
        if (lane < OW) {
            float acc = w0 * lz + w1 * lw
                      + w2 * v.x + w3 * v.y + w4 * v.z + w5 * v.w
                      + w6 * rx + w7 * ry;
            tmp[r * OW + lane] = acc;
        }
    }
    __syncthreads();

    // ---- vertical pass: 768 outputs, 3 per thread ----
    float* __restrict__ dst = out + (size_t)img_id * (OH * OW);
    #pragma unroll
    for (int i = 0; i < 3; i++) {
        const int o  = tid + 256 * i;
        const int oh = o / OW;
        const int ow = o - oh * OW;
        const int j0 = 4 * oh - 2;

        float u0 = 0.125f, u1 = 0.375f, u2 = 0.625f, u3 = 0.875f,
              u4 = 0.875f, u5 = 0.625f, u6 = 0.375f, u7 = 0.125f;
        float vn = 0.25f;
        if (oh == 0)      { u0 = 0.f; u1 = 0.f; vn = 1.f / 3.5f; }
        if (oh == OH - 1) { u6 = 0.f; u7 = 0.f; vn = 1.f / 3.5f; }

        // clamp indices for the zero-weight OOB taps (safe SMEM reads)
        const int ja = (j0     < 0) ? 0 : j0;
        const int jb = (j0 + 1 < 0) ? 0 : j0 + 1;
        const int jg = (j0 + 6 > HH - 1) ? HH - 1 : j0 + 6;
        const int jh = (j0 + 7 > HH - 1) ? HH - 1 : j0 + 7;

        float acc = u0 * tmp[ja * OW + ow]
                  + u1 * tmp[jb * OW + ow]
                  + u2 * tmp[(j0 + 2) * OW + ow]
                  + u3 * tmp[(j0 + 3) * OW + ow]
                  + u4 * tmp[(j0 + 4) * OW + ow]
                  + u5 * tmp[(j0 + 5) * OW + ow]
                  + u6 * tmp[jg * OW + ow]
                  + u7 * tmp[jh * OW + ow];
        dst[o] = acc * vn;
    }
}

extern "C" void kernel_launch(void* const* d_in, const int* in_sizes, int n_in,
                              void* d_out, int out_size) {
    const float* x = (const float*)d_in[0];   // (2048, 6, 128, 96) float32
    float* out = (float*)d_out;               // (2048, 6, 768) float32
    resize_aa_kernel<<<BB * CC, 256>>>(x, out);
}

// round 3
// speedup vs baseline: 2.0787x; 1.0043x over previous
#include <cuda_runtime.h>
#include <cuda_bf16.h>

// Batched antialiased bilinear resize (128,96) -> (32,24), scale 1/4.
// Separable triangle filter, support 4: output o samples s=4o+1.5, taps
// j=4o-2..4o+5, raw weights {1,3,5,7,7,5,3,1}/8, normalized by in-range tap
// sum (4.0 interior, 3.5 at first/last output).
//
// Horizontal pass in registers via warp shuffles (one LDG.128 per lane per
// row); only the 128x24 intermediate touches SMEM. Vertical pass vectorized:
// 192 threads each produce a float4 of output (8x LDS.128 + 1x STG.128).

#define BB   2048
#define CC   6
#define HH   128
#define WW   96
#define OH   32
#define OW   24

__global__ __launch_bounds__(256, 8)
void resize_aa_kernel(const float* __restrict__ x, float* __restrict__ out) {
    __shared__ float tmp[HH * OW];   // 12 KB horizontal intermediate

    const int img_id = blockIdx.x;   // 0 .. B*C-1
    const int tid  = threadIdx.x;
    const int wid  = tid >> 5;
    const int lane = tid & 31;
    const float* __restrict__ src = x + (size_t)img_id * (HH * WW);

    // ---- per-lane horizontal weights (norm folded in) ----
    const int oc = (lane < OW) ? lane : (OW - 1);   // lanes 24..31 shadow lane 23
    float w0 = 0.125f, w1 = 0.375f, w2 = 0.625f, w3 = 0.875f,
          w4 = 0.875f, w5 = 0.625f, w6 = 0.375f, w7 = 0.125f;
    float norm = 0.25f;
    if (oc == 0)      { w0 = 0.f; w1 = 0.f; norm = 1.f / 3.5f; }
    if (oc == OW - 1) { w6 = 0.f; w7 = 0.f; norm = 1.f / 3.5f; }
    w0 *= norm; w1 *= norm; w2 *= norm; w3 *= norm;
    w4 *= norm; w5 *= norm; w6 *= norm; w7 *= norm;

    // ---- horizontal pass: one warp per row, 16 rows per warp ----
    #pragma unroll
    for (int i = 0; i < HH / 8; i++) {
        const int r = wid + 8 * i;
        float4 v = *(const float4*)(src + r * WW + 4 * oc);
        float lz = __shfl_up_sync  (0xFFFFFFFFu, v.z, 1);
        float lw = __shfl_up_sync  (0xFFFFFFFFu, v.w, 1);
        float rx = __shfl_down_sync(0xFFFFFFFFu, v.x, 1);
        float ry = __shfl_down_sync(0xFFFFFFFFu, v.y, 1);
        if (lane < OW) {
            float acc = w0 * lz + w1 * lw
                      + w2 * v.x + w3 * v.y + w4 * v.z + w5 * v.w
                      + w6 * rx + w7 * ry;
            tmp[r * OW + lane] = acc;
        }
    }
    __syncthreads();

    // ---- vertical pass: 192 threads, one float4 (same oh, 4 ow) each ----
    if (tid < (OH * OW) / 4) {                 // 192
        const int oh  = tid / (OW / 4);        // 0..31
        const int q   = tid - oh * (OW / 4);   // 0..5
        const int j0  = 4 * oh - 2;

        float u0 = 0.125f, u1 = 0.375f, u2 = 0.625f, u3 = 0.875f,
              u4 = 0.875f, u5 = 0.625f, u6 = 0.375f, u7 = 0.125f;
        float vn = 0.25f;
        if (oh == 0)      { u0 = 0.f; u1 = 0.f; vn = 1.f / 3.5f; }
        if (oh == OH - 1) { u6 = 0.f; u7 = 0.f; vn = 1.f / 3.5f; }

        // clamp indices for the zero-weight OOB taps (safe SMEM reads)
        const int ja = (j0     < 0) ? 0 : j0;
        const int jb = (j0 + 1 < 0) ? 0 : j0 + 1;
        const int jg = (j0 + 6 > HH - 1) ? HH - 1 : j0 + 6;
        const int jh = (j0 + 7 > HH - 1) ? HH - 1 : j0 + 7;

        const float* base = tmp + 4 * q;
        float4 t0 = *(const float4*)(base + ja       * OW);
        float4 t1 = *(const float4*)(base + jb       * OW);
        float4 t2 = *(const float4*)(base + (j0 + 2) * OW);
        float4 t3 = *(const float4*)(base + (j0 + 3) * OW);
        float4 t4 = *(const float4*)(base + (j0 + 4) * OW);
        float4 t5 = *(const float4*)(base + (j0 + 5) * OW);
        float4 t6 = *(const float4*)(base + jg       * OW);
        float4 t7 = *(const float4*)(base + jh       * OW);

        float4 r;
        r.x = (u0*t0.x + u1*t1.x + u2*t2.x + u3*t3.x +
               u4*t4.x + u5*t5.x + u6*t6.x + u7*t7.x) * vn;
        r.y = (u0*t0.y + u1*t1.y + u2*t2.y + u3*t3.y +
               u4*t4.y + u5*t5.y + u6*t6.y + u7*t7.y) * vn;
        r.z = (u0*t0.z + u1*t1.z + u2*t2.z + u3*t3.z +
               u4*t4.z + u5*t5.z + u6*t6.z + u7*t7.z) * vn;
        r.w = (u0*t0.w + u1*t1.w + u2*t2.w + u3*t3.w +
               u4*t4.w + u5*t5.w + u6*t6.w + u7*t7.w) * vn;

        float* __restrict__ dst = out + (size_t)img_id * (OH * OW);
        *(float4*)(dst + 4 * tid) = r;
    }
}

extern "C" void kernel_launch(void* const* d_in, const int* in_sizes, int n_in,
                              void* d_out, int out_size) {
    const float* x = (const float*)d_in[0];   // (2048, 6, 128, 96) float32
    float* out = (float*)d_out;               // (2048, 6, 768) float32
    resize_aa_kernel<<<BB * CC, 256>>>(x, out);
}

// round 4
// speedup vs baseline: 2.2760x; 1.0949x over previous
#include <cuda_runtime.h>
#include <cuda_bf16.h>

// Batched antialiased bilinear resize (128,96) -> (32,24), scale 1/4.
// Separable triangle filter, support 4: output o samples s=4o+1.5, taps
// j=4o-2..4o+5, raw weights {1,3,5,7,7,5,3,1}/8, normalized by the in-range
// tap sum (4.0 interior, 3.5 at first/last output).
//
// Fully warp-synchronous: NO shared memory, NO __syncthreads.
// Vertical pass first, in registers: warp w owns output rows 4w..4w+3,
// reading input rows 16w-2..16w+17 (20 rows; 2-row overlap between warps is
// absorbed by L1/L2). Lane oc (0..23) holds the float4 of columns 4oc..4oc+3.
// Each completed output row is immediately horizontally filtered with 4 warp
// shuffles and stored. All filter weights are FFMA immediates.

#define BB   2048
#define CC   6
#define HH   128
#define WW   96
#define OH   32
#define OW   24

__global__ __launch_bounds__(256, 6)
void resize_aa_kernel(const float* __restrict__ x, float* __restrict__ out) {
    const int img  = blockIdx.x;            // 0 .. B*C-1
    const int tid  = threadIdx.x;
    const int w    = tid >> 5;              // warp 0..7 -> output rows 4w..4w+3
    const int lane = tid & 31;
    const int oc   = (lane < OW) ? lane : (OW - 1);  // lanes 24..31 shadow 23

    const float* __restrict__ src = x + (size_t)img * (HH * WW) + 4 * oc;
    float* __restrict__ dst = out + (size_t)img * (OH * OW);

    // raw vertical/horizontal tap weights (sum 4.0 when all in range)
    constexpr float WT[8] = {0.125f, 0.375f, 0.625f, 0.875f,
                             0.875f, 0.625f, 0.375f, 0.125f};
    constexpr float QTR  = 0.25f;        // interior norm (1/4.0)
    constexpr float EDGE = 1.0f / 3.5f;  // first/last output norm

    // per-lane horizontal norm
    const float hn = (oc == 0 || oc == OW - 1) ? EDGE : QTR;

    // horizontal filter + store for one vertically-filtered output row.
    // Lane oc holds a = columns 4oc..4oc+3; taps 4oc-2..4oc+5 come from
    // (lane-1).zw, own xyzw, (lane+1).xy. Edge taps are zeroed (renorm via hn).
    auto emit = [&](float4 a, int oh, float vn) {
        float lz = __shfl_up_sync  (0xFFFFFFFFu, a.z, 1);
        float lw = __shfl_up_sync  (0xFFFFFFFFu, a.w, 1);
        float rx = __shfl_down_sync(0xFFFFFFFFu, a.x, 1);
        float ry = __shfl_down_sync(0xFFFFFFFFu, a.y, 1);
        if (lane == 0)      { lz = 0.f; lw = 0.f; }
        if (lane == OW - 1) { rx = 0.f; ry = 0.f; }
        float res = 0.125f * lz + 0.375f * lw
                  + 0.625f * a.x + 0.875f * a.y + 0.875f * a.z + 0.625f * a.w
                  + 0.375f * rx + 0.125f * ry;
        if (lane < OW)
            dst[oh * OW + lane] = res * (vn * hn);
    };

    float4 a0 = {0.f, 0.f, 0.f, 0.f};
    float4 a1 = a0, a2 = a0, a3 = a0;

    const int rbase = 16 * w - 2;
    const float vn0 = (w == 0) ? EDGE : QTR;   // oh = 4w   (edge only at oh=0)
    const float vn3 = (w == 7) ? EDGE : QTR;   // oh = 4w+3 (edge only at oh=31)

    // Output oh=4w+a taps local rows jl = 4a .. 4a+7 (jl = global row - rbase).
    #pragma unroll
    for (int jl = 0; jl < 20; jl++) {
        const int r = rbase + jl;
        float4 v = {0.f, 0.f, 0.f, 0.f};
        // only jl<2 (w==0) and jl>=18 (w==7) can be out of range
        if ((jl >= 2 || r >= 0) && (jl < 18 || r < HH))
            v = *(const float4*)(src + r * WW);

        if (jl <= 7) {
            const float c = WT[jl];
            a0.x += c * v.x; a0.y += c * v.y; a0.z += c * v.z; a0.w += c * v.w;
        }
        if (jl >= 4 && jl <= 11) {
            const float c = WT[jl - 4];
            a1.x += c * v.x; a1.y += c * v.y; a1.z += c * v.z; a1.w += c * v.w;
        }
        if (jl >= 8 && jl <= 15) {
            const float c = WT[jl - 8];
            a2.x += c * v.x; a2.y += c * v.y; a2.z += c * v.z; a2.w += c * v.w;
        }
        if (jl >= 12) {
            const float c = WT[jl - 12];
            a3.x += c * v.x; a3.y += c * v.y; a3.z += c * v.z; a3.w += c * v.w;
        }

        // emit each output row as soon as its last tap is accumulated
        if (jl == 7)  emit(a0, 4 * w + 0, vn0);
        if (jl == 11) emit(a1, 4 * w + 1, QTR);
        if (jl == 15) emit(a2, 4 * w + 2, QTR);
        if (jl == 19) emit(a3, 4 * w + 3, vn3);
    }
}

extern "C" void kernel_launch(void* const* d_in, const int* in_sizes, int n_in,
                              void* d_out, int out_size) {
    const float* x = (const float*)d_in[0];   // (2048, 6, 128, 96) float32
    float* out = (float*)d_out;               // (2048, 6, 768) float32
    resize_aa_kernel<<<BB * CC, 256>>>(x, out);
}